// round 1
// baseline (speedup 1.0000x reference)
#include <cuda_runtime.h>
#include <math.h>

// Problem dims (fixed by the dataset)
#define MTOT   4096      // B*N
#define NSEQ   2048
#define DMODEL 1024
#define NHEAD  16
#define DHEAD  64

// Scratch (allocation-free rule: __device__ globals)
__device__ float g_Q[MTOT * DMODEL];
__device__ float g_K[MTOT * DMODEL];
__device__ float g_V[MTOT * DMODEL];
__device__ float g_A[MTOT * DMODEL];

// ---------------------------------------------------------------------------
// Register-blocked fp32 GEMM: C[M,N] = A[M,K] @ B[K,N] (+bias)
// 128x128 tile, BK=16, 256 threads, 8x8 per thread, reg-prefetch of next tile.
// srcsel: 0 -> A_in, 1 -> g_A.  dstsel: 0 -> C_out, 1/2/3 -> g_Q/g_K/g_V.
// ---------------------------------------------------------------------------
__global__ __launch_bounds__(256, 2)
void gemm128(const float* __restrict__ A_in, const float* __restrict__ B,
             const float* __restrict__ bias, float* __restrict__ C_out,
             int M, int N, int K, int srcsel, int dstsel)
{
    const float* __restrict__ A = (srcsel == 0) ? A_in : g_A;
    float* __restrict__ C = (dstsel == 0) ? C_out :
                            (dstsel == 1) ? g_Q  :
                            (dstsel == 2) ? g_K  : g_V;

    __shared__ float As[16][132];   // A tile transposed: As[k][m]
    __shared__ float Bs[16][128];   // Bs[k][n]

    const int tid = threadIdx.x;
    const int tx  = tid & 15;
    const int ty  = tid >> 4;
    const int bm  = blockIdx.y << 7;
    const int bn  = blockIdx.x << 7;

    // loader mapping (coalesced 64B chunks)
    const int arow = tid >> 2;          // 0..63
    const int akc  = (tid & 3) << 2;    // 0,4,8,12
    const int bkr  = tid >> 5;          // 0..7
    const int bnc  = (tid & 31) << 2;   // 0..124

    const float* Ap0 = A + (bm + arow) * K + akc;
    const float* Ap1 = A + (bm + arow + 64) * K + akc;
    const float* Bp0 = B + bkr * N + bn + bnc;
    const float* Bp1 = B + (bkr + 8) * N + bn + bnc;

    float acc[8][8];
#pragma unroll
    for (int i = 0; i < 8; i++)
#pragma unroll
        for (int j = 0; j < 8; j++) acc[i][j] = 0.f;

    const int nkt = K >> 4;
    float4 ra0 = *(const float4*)Ap0;
    float4 ra1 = *(const float4*)Ap1;
    float4 rb0 = *(const float4*)Bp0;
    float4 rb1 = *(const float4*)Bp1;

    for (int kt = 0; kt < nkt; kt++) {
        As[akc + 0][arow]      = ra0.x; As[akc + 1][arow]      = ra0.y;
        As[akc + 2][arow]      = ra0.z; As[akc + 3][arow]      = ra0.w;
        As[akc + 0][arow + 64] = ra1.x; As[akc + 1][arow + 64] = ra1.y;
        As[akc + 2][arow + 64] = ra1.z; As[akc + 3][arow + 64] = ra1.w;
        *(float4*)&Bs[bkr][bnc]     = rb0;
        *(float4*)&Bs[bkr + 8][bnc] = rb1;
        __syncthreads();

        if (kt + 1 < nkt) {
            const int ko = (kt + 1) << 4;
            ra0 = *(const float4*)(Ap0 + ko);
            ra1 = *(const float4*)(Ap1 + ko);
            rb0 = *(const float4*)(Bp0 + ko * N);
            rb1 = *(const float4*)(Bp1 + ko * N);
        }

#pragma unroll
        for (int k = 0; k < 16; k++) {
            float4 fa0 = *(const float4*)&As[k][ty * 8];
            float4 fa1 = *(const float4*)&As[k][ty * 8 + 4];
            float4 fb0 = *(const float4*)&Bs[k][tx * 8];
            float4 fb1 = *(const float4*)&Bs[k][tx * 8 + 4];
            float av[8] = {fa0.x, fa0.y, fa0.z, fa0.w, fa1.x, fa1.y, fa1.z, fa1.w};
            float bw[8] = {fb0.x, fb0.y, fb0.z, fb0.w, fb1.x, fb1.y, fb1.z, fb1.w};
#pragma unroll
            for (int i = 0; i < 8; i++)
#pragma unroll
                for (int j = 0; j < 8; j++)
                    acc[i][j] += av[i] * bw[j];
        }
        __syncthreads();
    }

    float bb[8];
    if (bias) {
        float4 t0 = *(const float4*)(bias + bn + tx * 8);
        float4 t1 = *(const float4*)(bias + bn + tx * 8 + 4);
        bb[0] = t0.x; bb[1] = t0.y; bb[2] = t0.z; bb[3] = t0.w;
        bb[4] = t1.x; bb[5] = t1.y; bb[6] = t1.z; bb[7] = t1.w;
    } else {
#pragma unroll
        for (int j = 0; j < 8; j++) bb[j] = 0.f;
    }

#pragma unroll
    for (int i = 0; i < 8; i++) {
        float* crow = C + (bm + ty * 8 + i) * N + bn + tx * 8;
        float4 r0 = make_float4(acc[i][0] + bb[0], acc[i][1] + bb[1],
                                acc[i][2] + bb[2], acc[i][3] + bb[3]);
        float4 r1 = make_float4(acc[i][4] + bb[4], acc[i][5] + bb[5],
                                acc[i][6] + bb[6], acc[i][7] + bb[7]);
        *(float4*)crow       = r0;
        *(float4*)(crow + 4) = r1;
    }
}

// ---------------------------------------------------------------------------
// Flash attention, fp32. One block = (batch,head, 64-query tile).
// 256 threads, 16x16 grid, 4x4 micro-tiles for both S=QK^T and O+=P·V.
// KP buffer is K^T during S-compute, then reused as P for the O-GEMM.
// Row statistics (m,l,alpha) kept per-lane, reduced via shfl over the 16-lane
// row group (lanes 0-15 / 16-31 of each warp) — no smem reductions.
// Smem = 3 * 64*64*4 = 48 KB exactly.
// ---------------------------------------------------------------------------
__global__ __launch_bounds__(256, 2)
void attn64()
{
    __shared__ float Qt[64][64];   // Q^T tile: Qt[d][i], pre-scaled by 1/8
    __shared__ float KP[64][64];   // K^T tile Kt[d][j]; later P tile Ps[i][t]
    __shared__ float Vs[64][64];   // V tile: Vs[t][dj]

    const int tid   = threadIdx.x;
    const int tx    = tid & 15;
    const int ty    = tid >> 4;
    const int qtile = blockIdx.x;          // 0..31
    const int b     = blockIdx.y >> 4;
    const int h     = blockIdx.y & 15;

    const int base = b * NSEQ * DMODEL + h * DHEAD;
    const int lrow = tid >> 2;             // 0..63
    const int lc0  = (tid & 3) << 2;       // 0,4,8,12 (+u*16)

    // --- load Q tile (scaled) into Qt[d][i] ---
    {
        const float* qrow = g_Q + base + (qtile * 64 + lrow) * DMODEL + lc0;
#pragma unroll
        for (int u = 0; u < 4; u++) {
            const int d0 = lc0 + u * 16;
            float4 q = *(const float4*)(qrow + u * 16);
            Qt[d0 + 0][lrow] = q.x * 0.125f;
            Qt[d0 + 1][lrow] = q.y * 0.125f;
            Qt[d0 + 2][lrow] = q.z * 0.125f;
            Qt[d0 + 3][lrow] = q.w * 0.125f;
        }
    }

    float m[4], l[4], o[4][4];
#pragma unroll
    for (int i = 0; i < 4; i++) {
        m[i] = -INFINITY; l[i] = 0.f;
#pragma unroll
        for (int j = 0; j < 4; j++) o[i][j] = 0.f;
    }

    for (int it = 0; it < NSEQ / 64; it++) {
        __syncthreads();   // previous iter fully consumed KP/Vs
        // --- load K (transposed) and V tiles ---
        {
            const float* krow = g_K + base + (it * 64 + lrow) * DMODEL + lc0;
            const float* vrow = g_V + base + (it * 64 + lrow) * DMODEL + lc0;
#pragma unroll
            for (int u = 0; u < 4; u++) {
                const int d0 = lc0 + u * 16;
                float4 kk = *(const float4*)(krow + u * 16);
                KP[d0 + 0][lrow] = kk.x; KP[d0 + 1][lrow] = kk.y;
                KP[d0 + 2][lrow] = kk.z; KP[d0 + 3][lrow] = kk.w;
                *(float4*)&Vs[lrow][d0] = *(const float4*)(vrow + u * 16);
            }
        }
        __syncthreads();

        // --- S = (Q*scale) K^T : s[4][4] over rows ty*4.., cols tx*4.. ---
        float s[4][4];
#pragma unroll
        for (int i = 0; i < 4; i++)
#pragma unroll
            for (int j = 0; j < 4; j++) s[i][j] = 0.f;

#pragma unroll 16
        for (int d = 0; d < 64; d++) {
            float4 a = *(const float4*)&Qt[d][ty << 2];
            float4 c = *(const float4*)&KP[d][tx << 2];
            float av[4] = {a.x, a.y, a.z, a.w};
            float cv[4] = {c.x, c.y, c.z, c.w};
#pragma unroll
            for (int i = 0; i < 4; i++)
#pragma unroll
                for (int j = 0; j < 4; j++)
                    s[i][j] += av[i] * cv[j];
        }

        // --- online softmax stats via shfl across the 16-lane row group ---
        float mn[4], al[4];
#pragma unroll
        for (int i = 0; i < 4; i++) {
            float lm = fmaxf(fmaxf(s[i][0], s[i][1]), fmaxf(s[i][2], s[i][3]));
            lm = fmaxf(lm, __shfl_xor_sync(0xFFFFFFFFu, lm, 1));
            lm = fmaxf(lm, __shfl_xor_sync(0xFFFFFFFFu, lm, 2));
            lm = fmaxf(lm, __shfl_xor_sync(0xFFFFFFFFu, lm, 4));
            lm = fmaxf(lm, __shfl_xor_sync(0xFFFFFFFFu, lm, 8));
            mn[i] = fmaxf(m[i], lm);
            al[i] = __expf(m[i] - mn[i]);   // exp(-inf)=0 on first tile
            m[i]  = mn[i];
        }

        // p = exp(s - m); row sums reduced via shfl
        float p[4][4];
#pragma unroll
        for (int i = 0; i < 4; i++) {
            p[i][0] = __expf(s[i][0] - mn[i]);
            p[i][1] = __expf(s[i][1] - mn[i]);
            p[i][2] = __expf(s[i][2] - mn[i]);
            p[i][3] = __expf(s[i][3] - mn[i]);
            float rs = p[i][0] + p[i][1] + p[i][2] + p[i][3];
            rs += __shfl_xor_sync(0xFFFFFFFFu, rs, 1);
            rs += __shfl_xor_sync(0xFFFFFFFFu, rs, 2);
            rs += __shfl_xor_sync(0xFFFFFFFFu, rs, 4);
            rs += __shfl_xor_sync(0xFFFFFFFFu, rs, 8);
            l[i] = l[i] * al[i] + rs;
        }

        __syncthreads();   // all S-compute reads of KP done; safe to overwrite as P
#pragma unroll
        for (int i = 0; i < 4; i++) {
            *(float4*)&KP[(ty << 2) + i][tx << 2] =
                make_float4(p[i][0], p[i][1], p[i][2], p[i][3]);
        }
        __syncthreads();   // P tile complete

        // --- O = O*alpha + P @ V ---
#pragma unroll
        for (int i = 0; i < 4; i++)
#pragma unroll
            for (int j = 0; j < 4; j++) o[i][j] *= al[i];

#pragma unroll 4
        for (int t4 = 0; t4 < 64; t4 += 4) {
            float4 pr[4], vr[4];
#pragma unroll
            for (int i = 0; i < 4; i++) pr[i] = *(const float4*)&KP[(ty << 2) + i][t4];
#pragma unroll
            for (int t = 0; t < 4; t++) vr[t] = *(const float4*)&Vs[t4 + t][tx << 2];
#pragma unroll
            for (int i = 0; i < 4; i++) {
                float pv[4] = {pr[i].x, pr[i].y, pr[i].z, pr[i].w};
#pragma unroll
                for (int t = 0; t < 4; t++) {
                    o[i][0] += pv[t] * vr[t].x;
                    o[i][1] += pv[t] * vr[t].y;
                    o[i][2] += pv[t] * vr[t].z;
                    o[i][3] += pv[t] * vr[t].w;
                }
            }
        }
    }

    // --- normalize and write [B,N,H*d] layout into g_A ---
#pragma unroll
    for (int i = 0; i < 4; i++) {
        const int r = (ty << 2) + i;
        const float inv = 1.0f / l[i];
        float4 rr = make_float4(o[i][0] * inv, o[i][1] * inv,
                                o[i][2] * inv, o[i][3] * inv);
        *(float4*)(g_A + base + (qtile * 64 + r) * DMODEL + (tx << 2)) = rr;
    }
}

// ---------------------------------------------------------------------------
extern "C" void kernel_launch(void* const* d_in, const int* in_sizes, int n_in,
                              void* d_out, int out_size)
{
    (void)in_sizes; (void)n_in; (void)out_size;
    const float* x  = (const float*)d_in[0];
    const float* Wq = (const float*)d_in[1];
    const float* Wk = (const float*)d_in[2];
    const float* Wv = (const float*)d_in[3];
    const float* Wo = (const float*)d_in[4];
    const float* bo = (const float*)d_in[5];
    float* out = (float*)d_out;

    dim3 ggrid(DMODEL / 128, MTOT / 128);   // (8, 32)
    gemm128<<<ggrid, 256>>>(x, Wq, nullptr, nullptr, MTOT, DMODEL, DMODEL, 0, 1);
    gemm128<<<ggrid, 256>>>(x, Wk, nullptr, nullptr, MTOT, DMODEL, DMODEL, 0, 2);
    gemm128<<<ggrid, 256>>>(x, Wv, nullptr, nullptr, MTOT, DMODEL, DMODEL, 0, 3);
    attn64<<<dim3(NSEQ / 64, 2 * NHEAD), 256>>>();
    gemm128<<<ggrid, 256>>>(nullptr, Wo, bo, out, MTOT, DMODEL, DMODEL, 1, 0);
}

// round 4
// speedup vs baseline: 5.8087x; 5.8087x over previous
#include <cuda_runtime.h>
#include <cuda_fp16.h>
#include <math.h>

#define MTOT   4096
#define NSEQ   2048
#define DMODEL 1024
#define NHEAD  16
#define DHEAD  64

// ---------------- scratch (allocation-free rule) ----------------
__device__ __half g_xh [MTOT * DMODEL];
__device__ __half g_Wqh[DMODEL * DMODEL];
__device__ __half g_Wkh[DMODEL * DMODEL];
__device__ __half g_Wvh[DMODEL * DMODEL];
__device__ __half g_Woh[DMODEL * DMODEL];
__device__ __half g_Qh [MTOT * DMODEL];
__device__ __half g_Kh [MTOT * DMODEL];
__device__ __half g_Vh [MTOT * DMODEL];
__device__ __half g_Ah [MTOT * DMODEL];

// ---------------- helpers ----------------
__device__ __forceinline__ unsigned sptr(const void* p)
{
    return (unsigned)__cvta_generic_to_shared(p);
}

__device__ __forceinline__ void ldm_x4(unsigned* r, unsigned a)
{
    asm volatile("ldmatrix.sync.aligned.m8n8.x4.shared.b16 {%0,%1,%2,%3}, [%4];"
                 : "=r"(r[0]), "=r"(r[1]), "=r"(r[2]), "=r"(r[3]) : "r"(a));
}

__device__ __forceinline__ void ldm_x4_t(unsigned* r, unsigned a)
{
    asm volatile("ldmatrix.sync.aligned.m8n8.x4.trans.shared.b16 {%0,%1,%2,%3}, [%4];"
                 : "=r"(r[0]), "=r"(r[1]), "=r"(r[2]), "=r"(r[3]) : "r"(a));
}

__device__ __forceinline__ void mma16816(float* d, const unsigned* a,
                                         unsigned b0, unsigned b1)
{
    asm volatile(
        "mma.sync.aligned.m16n8k16.row.col.f32.f16.f16.f32 "
        "{%0,%1,%2,%3},{%4,%5,%6,%7},{%8,%9},{%0,%1,%2,%3};"
        : "+f"(d[0]), "+f"(d[1]), "+f"(d[2]), "+f"(d[3])
        : "r"(a[0]), "r"(a[1]), "r"(a[2]), "r"(a[3]), "r"(b0), "r"(b1));
}

__device__ __forceinline__ unsigned pack_h2(float x, float y)
{
    __half2 t = __floats2half2_rn(x, y);
    return *(unsigned*)&t;
}

// Load one A-style 16x16 fragment (non-trans) from smem tile base.
// row0: first matrix row; col0: first k column; str: halfs per smem row.
__device__ __forceinline__ void frag_a(unsigned* fr, const __half* base,
                                       int str, int row0, int col0, int lane)
{
    int gg = lane >> 3;
    int lr = lane & 7;
    int row = row0 + (gg & 1) * 8 + lr;
    int col = col0 + (gg >> 1) * 8;
    ldm_x4(fr, sptr(base + row * str + col));
}

// Load B-fragments for 16 n-values from K-rows-as-n smem [n][k] (non-trans).
// r4: r0,r1 = first 8 n (k0-7 / k8-15); r2,r3 = next 8 n.
__device__ __forceinline__ void frag_b_nk(unsigned* fr4, const __half* base,
                                          int str, int n0, int k0, int lane)
{
    int gg = lane >> 3;
    int lr = lane & 7;
    int row = n0 + (gg >> 1) * 8 + lr;
    int col = k0 + (gg & 1) * 8;
    ldm_x4(fr4, sptr(base + row * str + col));
}

// Load B-fragments for 16 n-values from row-major [k][n] smem (trans).
__device__ __forceinline__ void frag_b_kn(unsigned* fr4, const __half* base,
                                          int str, int k0, int n0, int lane)
{
    int gg = lane >> 3;
    int lr = lane & 7;
    int row = k0 + (gg & 1) * 8 + lr;
    int col = n0 + (gg >> 1) * 8;
    ldm_x4_t(fr4, sptr(base + row * str + col));
}

// ---------------- fp32 -> fp16 conversion ----------------
__global__ void cvt_f2h(const float* __restrict__ src, int dsel, int n4)
{
    __half* dst;
    if (dsel == 0)      dst = g_xh;
    else if (dsel == 1) dst = g_Wqh;
    else if (dsel == 2) dst = g_Wkh;
    else if (dsel == 3) dst = g_Wvh;
    else                dst = g_Woh;

    int i = blockIdx.x * blockDim.x + threadIdx.x;
    if (i < n4) {
        float4 v = ((const float4*)src)[i];
        __half2* dp = (__half2*)dst;
        dp[2 * i]     = __floats2half2_rn(v.x, v.y);
        dp[2 * i + 1] = __floats2half2_rn(v.z, v.w);
    }
}

// ---------------- fp16 tensor-core GEMM: 128x128x32 tiles ----------------
#define ASTR 40
#define BSTR 136

__global__ __launch_bounds__(256, 2)
void gemm_h(int asel, int bsel, int dsel,
            float* __restrict__ Cf, const float* __restrict__ bias)
{
    const __half* __restrict__ A = (asel == 0) ? g_xh : g_Ah;
    const __half* __restrict__ B;
    if (bsel == 0)      B = g_Wqh;
    else if (bsel == 1) B = g_Wkh;
    else if (bsel == 2) B = g_Wvh;
    else                B = g_Woh;
    __half* __restrict__ Ch;
    if (dsel == 0)      Ch = g_Qh;
    else if (dsel == 1) Ch = g_Kh;
    else if (dsel == 2) Ch = g_Vh;
    else                Ch = (__half*)0;

    __shared__ __align__(16) __half As[128 * ASTR];
    __shared__ __align__(16) __half Bs[32 * BSTR];

    const int tid  = threadIdx.x;
    const int lane = tid & 31;
    const int wid  = tid >> 5;
    const int wm   = (wid >> 1) * 32;
    const int wn   = (wid & 1) * 64;
    const int bm   = blockIdx.y * 128;
    const int bn   = blockIdx.x * 128;

    const int ar = tid >> 2;
    const int ac = (tid & 3) * 8;
    const int br = tid >> 4;
    const int bc = (tid & 15) * 8;

    const __half* Ap0 = A + (size_t)(bm + ar) * DMODEL + ac;
    const __half* Ap1 = Ap0 + (size_t)64 * DMODEL;
    const __half* Bp0 = B + (size_t)br * DMODEL + bn + bc;
    const __half* Bp1 = Bp0 + (size_t)16 * DMODEL;

    float acc[2][8][4];
    for (int mt = 0; mt < 2; mt++)
        for (int nt = 0; nt < 8; nt++)
            for (int c = 0; c < 4; c++)
                acc[mt][nt][c] = 0.f;

    uint4 ra0 = *(const uint4*)Ap0;
    uint4 ra1 = *(const uint4*)Ap1;
    uint4 rb0 = *(const uint4*)Bp0;
    uint4 rb1 = *(const uint4*)Bp1;

    const int NKT = DMODEL / 32;
    for (int kt = 0; kt < NKT; kt++) {
        *(uint4*)&As[ar * ASTR + ac]        = ra0;
        *(uint4*)&As[(ar + 64) * ASTR + ac] = ra1;
        *(uint4*)&Bs[br * BSTR + bc]        = rb0;
        *(uint4*)&Bs[(br + 16) * BSTR + bc] = rb1;
        __syncthreads();

        if (kt + 1 < NKT) {
            int ko = (kt + 1) * 32;
            ra0 = *(const uint4*)(Ap0 + ko);
            ra1 = *(const uint4*)(Ap1 + ko);
            rb0 = *(const uint4*)(Bp0 + (size_t)ko * DMODEL);
            rb1 = *(const uint4*)(Bp1 + (size_t)ko * DMODEL);
        }

#pragma unroll
        for (int ks = 0; ks < 2; ks++) {
            int k0 = ks * 16;
            unsigned af0[4];
            unsigned af1[4];
            frag_a(af0, As, ASTR, wm,      k0, lane);
            frag_a(af1, As, ASTR, wm + 16, k0, lane);
            unsigned bf[16];
#pragma unroll
            for (int ntp = 0; ntp < 4; ntp++)
                frag_b_kn(bf + 4 * ntp, Bs, BSTR, k0, wn + ntp * 16, lane);
#pragma unroll
            for (int nt = 0; nt < 8; nt++) {
                unsigned bx = bf[(nt >> 1) * 4 + (nt & 1) * 2];
                unsigned by = bf[(nt >> 1) * 4 + (nt & 1) * 2 + 1];
                mma16816(acc[0][nt], af0, bx, by);
                mma16816(acc[1][nt], af1, bx, by);
            }
        }
        __syncthreads();
    }

    const int er = lane >> 2;
    const int ec = (lane & 3) * 2;
    if (dsel < 3) {
        for (int mt = 0; mt < 2; mt++) {
            for (int nt = 0; nt < 8; nt++) {
                size_t row = (size_t)(bm + wm + mt * 16 + er);
                int    col = bn + wn + nt * 8 + ec;
                *(__half2*)&Ch[row * DMODEL + col] =
                    __floats2half2_rn(acc[mt][nt][0], acc[mt][nt][1]);
                *(__half2*)&Ch[(row + 8) * DMODEL + col] =
                    __floats2half2_rn(acc[mt][nt][2], acc[mt][nt][3]);
            }
        }
    } else {
        for (int mt = 0; mt < 2; mt++) {
            for (int nt = 0; nt < 8; nt++) {
                size_t row = (size_t)(bm + wm + mt * 16 + er);
                int    col = bn + wn + nt * 8 + ec;
                float bv0 = bias[col];
                float bv1 = bias[col + 1];
                *(float2*)&Cf[row * DMODEL + col] =
                    make_float2(acc[mt][nt][0] + bv0, acc[mt][nt][1] + bv1);
                *(float2*)&Cf[(row + 8) * DMODEL + col] =
                    make_float2(acc[mt][nt][2] + bv0, acc[mt][nt][3] + bv1);
            }
        }
    }
}

// ---------------- flash attention, fp16 tensor cores ----------------
#define KSTR 72

__global__ __launch_bounds__(128, 4)
void attn_h()
{
    __shared__ __align__(16) __half Ks[64 * KSTR];
    __shared__ __align__(16) __half Vs[64 * KSTR];

    const int tid   = threadIdx.x;
    const int lane  = tid & 31;
    const int wid   = tid >> 5;
    const int qtile = blockIdx.x;
    const int bi    = blockIdx.y >> 4;
    const int hh    = blockIdx.y & 15;

    const __half* Qb = g_Qh + (size_t)(bi * NSEQ + qtile * 64) * DMODEL + hh * DHEAD;
    const __half* Kb = g_Kh + (size_t)(bi * NSEQ) * DMODEL + hh * DHEAD;
    const __half* Vb = g_Vh + (size_t)(bi * NSEQ) * DMODEL + hh * DHEAD;

    const int srow = tid >> 3;
    const int scol = (tid & 7) * 8;

    // stage Q tile into Ks, extract persistent A-fragments
#pragma unroll
    for (int u = 0; u < 4; u++) {
        int row = srow + u * 16;
        *(uint4*)&Ks[row * KSTR + scol] =
            *(const uint4*)(Qb + (size_t)row * DMODEL + scol);
    }
    __syncthreads();

    unsigned qa[4][4];
#pragma unroll
    for (int kk = 0; kk < 4; kk++)
        frag_a(qa[kk], Ks, KSTR, wid * 16, kk * 16, lane);

    float m0 = -1e30f;
    float m1 = -1e30f;
    float l0 = 0.f;
    float l1 = 0.f;
    float o[8][4];
    for (int nt = 0; nt < 8; nt++)
        for (int c = 0; c < 4; c++)
            o[nt][c] = 0.f;

    for (int it = 0; it < NSEQ / 64; it++) {
        __syncthreads();
        const __half* Kt = Kb + (size_t)it * 64 * DMODEL;
        const __half* Vt = Vb + (size_t)it * 64 * DMODEL;
#pragma unroll
        for (int u = 0; u < 4; u++) {
            int row = srow + u * 16;
            *(uint4*)&Ks[row * KSTR + scol] =
                *(const uint4*)(Kt + (size_t)row * DMODEL + scol);
            *(uint4*)&Vs[row * KSTR + scol] =
                *(const uint4*)(Vt + (size_t)row * DMODEL + scol);
        }
        __syncthreads();

        // S = Q K^T
        float s[8][4];
        for (int nt = 0; nt < 8; nt++)
            for (int c = 0; c < 4; c++)
                s[nt][c] = 0.f;

#pragma unroll
        for (int kk = 0; kk < 4; kk++) {
            unsigned bf[16];
#pragma unroll
            for (int ntp = 0; ntp < 4; ntp++)
                frag_b_nk(bf + 4 * ntp, Ks, KSTR, ntp * 16, kk * 16, lane);
#pragma unroll
            for (int nt = 0; nt < 8; nt++) {
                unsigned bx = bf[(nt >> 1) * 4 + (nt & 1) * 2];
                unsigned by = bf[(nt >> 1) * 4 + (nt & 1) * 2 + 1];
                mma16816(s[nt], qa[kk], bx, by);
            }
        }

        // online softmax over the 4-lane row group
        float mx0 = -1e30f;
        float mx1 = -1e30f;
#pragma unroll
        for (int nt = 0; nt < 8; nt++) {
            s[nt][0] *= 0.125f;
            s[nt][1] *= 0.125f;
            s[nt][2] *= 0.125f;
            s[nt][3] *= 0.125f;
            mx0 = fmaxf(mx0, fmaxf(s[nt][0], s[nt][1]));
            mx1 = fmaxf(mx1, fmaxf(s[nt][2], s[nt][3]));
        }
        mx0 = fmaxf(mx0, __shfl_xor_sync(0xFFFFFFFFu, mx0, 1));
        mx0 = fmaxf(mx0, __shfl_xor_sync(0xFFFFFFFFu, mx0, 2));
        mx1 = fmaxf(mx1, __shfl_xor_sync(0xFFFFFFFFu, mx1, 1));
        mx1 = fmaxf(mx1, __shfl_xor_sync(0xFFFFFFFFu, mx1, 2));

        float mn0 = fmaxf(m0, mx0);
        float mn1 = fmaxf(m1, mx1);
        float al0 = __expf(m0 - mn0);
        float al1 = __expf(m1 - mn1);
        m0 = mn0;
        m1 = mn1;

        float rs0 = 0.f;
        float rs1 = 0.f;
#pragma unroll
        for (int nt = 0; nt < 8; nt++) {
            s[nt][0] = __expf(s[nt][0] - mn0);
            s[nt][1] = __expf(s[nt][1] - mn0);
            s[nt][2] = __expf(s[nt][2] - mn1);
            s[nt][3] = __expf(s[nt][3] - mn1);
            rs0 += s[nt][0] + s[nt][1];
            rs1 += s[nt][2] + s[nt][3];
        }
        rs0 += __shfl_xor_sync(0xFFFFFFFFu, rs0, 1);
        rs0 += __shfl_xor_sync(0xFFFFFFFFu, rs0, 2);
        rs1 += __shfl_xor_sync(0xFFFFFFFFu, rs1, 1);
        rs1 += __shfl_xor_sync(0xFFFFFFFFu, rs1, 2);
        l0 = l0 * al0 + rs0;
        l1 = l1 * al1 + rs1;

#pragma unroll
        for (int nt = 0; nt < 8; nt++) {
            o[nt][0] *= al0;
            o[nt][1] *= al0;
            o[nt][2] *= al1;
            o[nt][3] *= al1;
        }

        // O += P V : P A-frags directly from S registers
#pragma unroll
        for (int kk = 0; kk < 4; kk++) {
            unsigned pa[4];
            pa[0] = pack_h2(s[2 * kk][0],     s[2 * kk][1]);
            pa[1] = pack_h2(s[2 * kk][2],     s[2 * kk][3]);
            pa[2] = pack_h2(s[2 * kk + 1][0], s[2 * kk + 1][1]);
            pa[3] = pack_h2(s[2 * kk + 1][2], s[2 * kk + 1][3]);

            unsigned bf[16];
#pragma unroll
            for (int ntp = 0; ntp < 4; ntp++)
                frag_b_kn(bf + 4 * ntp, Vs, KSTR, kk * 16, ntp * 16, lane);
#pragma unroll
            for (int nt = 0; nt < 8; nt++) {
                unsigned bx = bf[(nt >> 1) * 4 + (nt & 1) * 2];
                unsigned by = bf[(nt >> 1) * 4 + (nt & 1) * 2 + 1];
                mma16816(o[nt], pa, bx, by);
            }
        }
    }

    // normalize + write fp16 [B*N, H*d]
    float inv0 = 1.f / l0;
    float inv1 = 1.f / l1;
    const int er = lane >> 2;
    const int ec = (lane & 3) * 2;
    __half* Ab = g_Ah + (size_t)(bi * NSEQ + qtile * 64 + wid * 16) * DMODEL + hh * DHEAD;
    for (int nt = 0; nt < 8; nt++) {
        int col = nt * 8 + ec;
        *(__half2*)&Ab[(size_t)er * DMODEL + col] =
            __floats2half2_rn(o[nt][0] * inv0, o[nt][1] * inv0);
        *(__half2*)&Ab[(size_t)(er + 8) * DMODEL + col] =
            __floats2half2_rn(o[nt][2] * inv1, o[nt][3] * inv1);
    }
}

// ---------------------------------------------------------------------------
extern "C" void kernel_launch(void* const* d_in, const int* in_sizes, int n_in,
                              void* d_out, int out_size)
{
    (void)in_sizes; (void)n_in; (void)out_size;
    const float* x  = (const float*)d_in[0];
    const float* Wq = (const float*)d_in[1];
    const float* Wk = (const float*)d_in[2];
    const float* Wv = (const float*)d_in[3];
    const float* Wo = (const float*)d_in[4];
    const float* bo = (const float*)d_in[5];
    float* out = (float*)d_out;

    cvt_f2h<<<4096, 256>>>(x,  0, MTOT * DMODEL / 4);
    cvt_f2h<<<1024, 256>>>(Wq, 1, DMODEL * DMODEL / 4);
    cvt_f2h<<<1024, 256>>>(Wk, 2, DMODEL * DMODEL / 4);
    cvt_f2h<<<1024, 256>>>(Wv, 3, DMODEL * DMODEL / 4);
    cvt_f2h<<<1024, 256>>>(Wo, 4, DMODEL * DMODEL / 4);

    dim3 ggrid(DMODEL / 128, MTOT / 128);
    gemm_h<<<ggrid, 256>>>(0, 0, 0, (float*)0, (const float*)0);
    gemm_h<<<ggrid, 256>>>(0, 1, 1, (float*)0, (const float*)0);
    gemm_h<<<ggrid, 256>>>(0, 2, 2, (float*)0, (const float*)0);
    attn_h<<<dim3(NSEQ / 64, 2 * NHEAD), 128>>>();
    gemm_h<<<ggrid, 256>>>(1, 3, 3, out, bo);
}

// round 6
// speedup vs baseline: 6.2933x; 1.0834x over previous
#include <cuda_runtime.h>
#include <cuda_fp16.h>
#include <math.h>
#include <stdint.h>

#define MTOT   4096
#define NSEQ   2048
#define DMODEL 1024
#define NHEAD  16
#define DHEAD  64

// ---------------- scratch (allocation-free rule) ----------------
__device__ __half g_xh [MTOT * DMODEL];
__device__ __half g_Wqh[DMODEL * DMODEL];
__device__ __half g_Wkh[DMODEL * DMODEL];
__device__ __half g_Wvh[DMODEL * DMODEL];
__device__ __half g_Woh[DMODEL * DMODEL];
__device__ __half g_Qh [MTOT * DMODEL];   // pre-scaled by 1/8
__device__ __half g_Kh [MTOT * DMODEL];
__device__ __half g_Vh [MTOT * DMODEL];
__device__ __half g_Ah [MTOT * DMODEL];

// ---------------- helpers ----------------
__device__ __forceinline__ unsigned sptr(const void* p)
{
    return (unsigned)__cvta_generic_to_shared(p);
}

__device__ __forceinline__ void ldm_x4(unsigned* r, unsigned a)
{
    asm volatile("ldmatrix.sync.aligned.m8n8.x4.shared.b16 {%0,%1,%2,%3}, [%4];"
                 : "=r"(r[0]), "=r"(r[1]), "=r"(r[2]), "=r"(r[3]) : "r"(a));
}

__device__ __forceinline__ void ldm_x4_t(unsigned* r, unsigned a)
{
    asm volatile("ldmatrix.sync.aligned.m8n8.x4.trans.shared.b16 {%0,%1,%2,%3}, [%4];"
                 : "=r"(r[0]), "=r"(r[1]), "=r"(r[2]), "=r"(r[3]) : "r"(a));
}

__device__ __forceinline__ void mma16816(float* d, const unsigned* a,
                                         unsigned b0, unsigned b1)
{
    asm volatile(
        "mma.sync.aligned.m16n8k16.row.col.f32.f16.f16.f32 "
        "{%0,%1,%2,%3},{%4,%5,%6,%7},{%8,%9},{%0,%1,%2,%3};"
        : "+f"(d[0]), "+f"(d[1]), "+f"(d[2]), "+f"(d[3])
        : "r"(a[0]), "r"(a[1]), "r"(a[2]), "r"(a[3]), "r"(b0), "r"(b1));
}

__device__ __forceinline__ unsigned pack_h2(float x, float y)
{
    __half2 t = __floats2half2_rn(x, y);
    return *(unsigned*)&t;
}

__device__ __forceinline__ void cpa16(unsigned dst, const void* src)
{
    asm volatile("cp.async.cg.shared.global [%0], [%1], 16;"
                 :: "r"(dst), "l"(__cvta_generic_to_global(src)) : "memory");
}

__device__ __forceinline__ void cpa_commit()
{
    asm volatile("cp.async.commit_group;" ::: "memory");
}

__device__ __forceinline__ void cpa_wait0()
{
    asm volatile("cp.async.wait_group 0;" ::: "memory");
}

__device__ __forceinline__ void cpa_wait1()
{
    asm volatile("cp.async.wait_group 1;" ::: "memory");
}

__device__ __forceinline__ void frag_a(unsigned* fr, const __half* base,
                                       int str, int row0, int col0, int lane)
{
    int gg = lane >> 3;
    int lr = lane & 7;
    int row = row0 + (gg & 1) * 8 + lr;
    int col = col0 + (gg >> 1) * 8;
    ldm_x4(fr, sptr(base + row * str + col));
}

__device__ __forceinline__ void frag_b_nk(unsigned* fr4, const __half* base,
                                          int str, int n0, int k0, int lane)
{
    int gg = lane >> 3;
    int lr = lane & 7;
    int row = n0 + (gg >> 1) * 8 + lr;
    int col = k0 + (gg & 1) * 8;
    ldm_x4(fr4, sptr(base + row * str + col));
}

__device__ __forceinline__ void frag_b_kn(unsigned* fr4, const __half* base,
                                          int str, int k0, int n0, int lane)
{
    int gg = lane >> 3;
    int lr = lane & 7;
    int row = k0 + (gg & 1) * 8 + lr;
    int col = n0 + (gg >> 1) * 8;
    ldm_x4_t(fr4, sptr(base + row * str + col));
}

// ---------------- single fused fp32 -> fp16 conversion ----------------
// chunks: x = 1048576 float4, then 4 weights x 262144 float4 each.
__global__ void cvt_all(const float* __restrict__ x,
                        const float* __restrict__ Wq,
                        const float* __restrict__ Wk,
                        const float* __restrict__ Wv,
                        const float* __restrict__ Wo)
{
    int i = blockIdx.x * blockDim.x + threadIdx.x;
    const float* src;
    __half2* dst;
    int j;
    if (i < 1048576) {
        src = x;  dst = (__half2*)g_xh;  j = i;
    } else {
        int t = i - 1048576;
        int w = t >> 18;
        j = t & 262143;
        if (w == 0)      { src = Wq; dst = (__half2*)g_Wqh; }
        else if (w == 1) { src = Wk; dst = (__half2*)g_Wkh; }
        else if (w == 2) { src = Wv; dst = (__half2*)g_Wvh; }
        else             { src = Wo; dst = (__half2*)g_Woh; }
    }
    float4 v = ((const float4*)src)[j];
    dst[2 * j]     = __floats2half2_rn(v.x, v.y);
    dst[2 * j + 1] = __floats2half2_rn(v.z, v.w);
}

// ---------------- fp16 tensor-core GEMM: 128x128x32 tiles ----------------
// qkv != 0: sel = blockIdx.z (0/1/2 -> Q/K/V). qkv == 0: sel = dsel_in.
// sel 0..2: fp16 out to g_Qh/g_Kh/g_Vh (Q pre-scaled by 1/8).
// sel 3: A = g_Ah, B = Wo, fp32 out + bias.
#define ASTR 40
#define BSTR 136

__global__ __launch_bounds__(256, 2)
void gemm_h(int qkv, int dsel_in,
            float* __restrict__ Cf, const float* __restrict__ bias)
{
    const int sel = qkv ? (int)blockIdx.z : dsel_in;

    const __half* __restrict__ A = (sel == 3) ? g_Ah : g_xh;
    const __half* __restrict__ B;
    if (sel == 0)      B = g_Wqh;
    else if (sel == 1) B = g_Wkh;
    else if (sel == 2) B = g_Wvh;
    else               B = g_Woh;
    __half* __restrict__ Ch;
    if (sel == 0)      Ch = g_Qh;
    else if (sel == 1) Ch = g_Kh;
    else if (sel == 2) Ch = g_Vh;
    else               Ch = (__half*)0;

    __shared__ __align__(16) __half As[128 * ASTR];
    __shared__ __align__(16) __half Bs[32 * BSTR];

    const int tid  = threadIdx.x;
    const int lane = tid & 31;
    const int wid  = tid >> 5;
    const int wm   = (wid >> 1) * 32;
    const int wn   = (wid & 1) * 64;
    const int bm   = blockIdx.y * 128;
    const int bn   = blockIdx.x * 128;

    const int ar = tid >> 2;
    const int ac = (tid & 3) * 8;
    const int br = tid >> 4;
    const int bc = (tid & 15) * 8;

    const __half* Ap0 = A + (size_t)(bm + ar) * DMODEL + ac;
    const __half* Ap1 = Ap0 + (size_t)64 * DMODEL;
    const __half* Bp0 = B + (size_t)br * DMODEL + bn + bc;
    const __half* Bp1 = Bp0 + (size_t)16 * DMODEL;

    float acc[2][8][4];
    for (int mt = 0; mt < 2; mt++)
        for (int nt = 0; nt < 8; nt++)
            for (int c = 0; c < 4; c++)
                acc[mt][nt][c] = 0.f;

    uint4 ra0 = *(const uint4*)Ap0;
    uint4 ra1 = *(const uint4*)Ap1;
    uint4 rb0 = *(const uint4*)Bp0;
    uint4 rb1 = *(const uint4*)Bp1;

    const int NKT = DMODEL / 32;
    for (int kt = 0; kt < NKT; kt++) {
        *(uint4*)&As[ar * ASTR + ac]        = ra0;
        *(uint4*)&As[(ar + 64) * ASTR + ac] = ra1;
        *(uint4*)&Bs[br * BSTR + bc]        = rb0;
        *(uint4*)&Bs[(br + 16) * BSTR + bc] = rb1;
        __syncthreads();

        if (kt + 1 < NKT) {
            int ko = (kt + 1) * 32;
            ra0 = *(const uint4*)(Ap0 + ko);
            ra1 = *(const uint4*)(Ap1 + ko);
            rb0 = *(const uint4*)(Bp0 + (size_t)ko * DMODEL);
            rb1 = *(const uint4*)(Bp1 + (size_t)ko * DMODEL);
        }

#pragma unroll
        for (int ks = 0; ks < 2; ks++) {
            int k0 = ks * 16;
            unsigned af0[4];
            unsigned af1[4];
            frag_a(af0, As, ASTR, wm,      k0, lane);
            frag_a(af1, As, ASTR, wm + 16, k0, lane);
            unsigned bf[16];
#pragma unroll
            for (int ntp = 0; ntp < 4; ntp++)
                frag_b_kn(bf + 4 * ntp, Bs, BSTR, k0, wn + ntp * 16, lane);
#pragma unroll
            for (int nt = 0; nt < 8; nt++) {
                unsigned bx = bf[(nt >> 1) * 4 + (nt & 1) * 2];
                unsigned by = bf[(nt >> 1) * 4 + (nt & 1) * 2 + 1];
                mma16816(acc[0][nt], af0, bx, by);
                mma16816(acc[1][nt], af1, bx, by);
            }
        }
        __syncthreads();
    }

    const int er = lane >> 2;
    const int ec = (lane & 3) * 2;
    if (sel < 3) {
        const float sc = (sel == 0) ? 0.125f : 1.0f;   // fold attention scale into Q
        for (int mt = 0; mt < 2; mt++) {
            for (int nt = 0; nt < 8; nt++) {
                size_t row = (size_t)(bm + wm + mt * 16 + er);
                int    col = bn + wn + nt * 8 + ec;
                *(__half2*)&Ch[row * DMODEL + col] =
                    __floats2half2_rn(acc[mt][nt][0] * sc, acc[mt][nt][1] * sc);
                *(__half2*)&Ch[(row + 8) * DMODEL + col] =
                    __floats2half2_rn(acc[mt][nt][2] * sc, acc[mt][nt][3] * sc);
            }
        }
    } else {
        for (int mt = 0; mt < 2; mt++) {
            for (int nt = 0; nt < 8; nt++) {
                size_t row = (size_t)(bm + wm + mt * 16 + er);
                int    col = bn + wn + nt * 8 + ec;
                float bv0 = bias[col];
                float bv1 = bias[col + 1];
                *(float2*)&Cf[row * DMODEL + col] =
                    make_float2(acc[mt][nt][0] + bv0, acc[mt][nt][1] + bv1);
                *(float2*)&Cf[(row + 8) * DMODEL + col] =
                    make_float2(acc[mt][nt][2] + bv0, acc[mt][nt][3] + bv1);
            }
        }
    }
}

// ---------------- flash attention, fp16 mma.sync, cp.async double buffer ----------------
#define KSTR 72
#define NTILES (NSEQ / 64)

__global__ __launch_bounds__(128, 4)
void attn_h()
{
    __shared__ __align__(16) __half Ks[2][64 * KSTR];
    __shared__ __align__(16) __half Vs[2][64 * KSTR];

    const int tid   = threadIdx.x;
    const int lane  = tid & 31;
    const int wid   = tid >> 5;
    const int qtile = blockIdx.x;
    const int bi    = blockIdx.y >> 4;
    const int hh    = blockIdx.y & 15;

    const __half* Qb = g_Qh + (size_t)(bi * NSEQ + qtile * 64) * DMODEL + hh * DHEAD;
    const __half* Kb = g_Kh + (size_t)(bi * NSEQ) * DMODEL + hh * DHEAD;
    const __half* Vb = g_Vh + (size_t)(bi * NSEQ) * DMODEL + hh * DHEAD;

    const int srow = tid >> 3;          // 0..15
    const int scol = (tid & 7) * 8;     // 0..56

    // stage Q tile into Ks[0], extract persistent A-fragments (Q pre-scaled)
#pragma unroll
    for (int u = 0; u < 4; u++) {
        int row = srow + u * 16;
        *(uint4*)&Ks[0][row * KSTR + scol] =
            *(const uint4*)(Qb + (size_t)row * DMODEL + scol);
    }
    __syncthreads();

    unsigned qa[4][4];
#pragma unroll
    for (int kk = 0; kk < 4; kk++)
        frag_a(qa[kk], Ks[0], KSTR, wid * 16, kk * 16, lane);
    __syncthreads();   // all Q frags extracted before buffer 0 is overwritten

    // cp.async loader for one 64-key tile (K + V) into buffer bf
    auto load_kv = [&](int it, int bf) {
        const __half* Kt = Kb + (size_t)it * 64 * DMODEL;
        const __half* Vt = Vb + (size_t)it * 64 * DMODEL;
#pragma unroll
        for (int u = 0; u < 4; u++) {
            int row = srow + u * 16;
            unsigned off = (unsigned)(row * KSTR + scol);
            cpa16(sptr(&Ks[bf][off]), Kt + (size_t)row * DMODEL + scol);
            cpa16(sptr(&Vs[bf][off]), Vt + (size_t)row * DMODEL + scol);
        }
        cpa_commit();
    };

    float m0 = -1e30f;
    float m1 = -1e30f;
    float l0 = 0.f;
    float l1 = 0.f;
    float o[8][4];
    for (int nt = 0; nt < 8; nt++)
        for (int c = 0; c < 4; c++)
            o[nt][c] = 0.f;

    load_kv(0, 0);

    for (int it = 0; it < NTILES; it++) {
        const int buf = it & 1;
        if (it + 1 < NTILES) {
            load_kv(it + 1, buf ^ 1);   // prior reads of buf^1 done (end-of-iter sync)
            cpa_wait1();                // tile `it` group complete
        } else {
            cpa_wait0();
        }
        __syncthreads();

        const __half* Kp = Ks[buf];
        const __half* Vp = Vs[buf];

        // S = (Q/8) K^T
        float s[8][4];
        for (int nt = 0; nt < 8; nt++)
            for (int c = 0; c < 4; c++)
                s[nt][c] = 0.f;

#pragma unroll
        for (int kk = 0; kk < 4; kk++) {
            unsigned bfr[16];
#pragma unroll
            for (int ntp = 0; ntp < 4; ntp++)
                frag_b_nk(bfr + 4 * ntp, Kp, KSTR, ntp * 16, kk * 16, lane);
#pragma unroll
            for (int nt = 0; nt < 8; nt++) {
                unsigned bx = bfr[(nt >> 1) * 4 + (nt & 1) * 2];
                unsigned by = bfr[(nt >> 1) * 4 + (nt & 1) * 2 + 1];
                mma16816(s[nt], qa[kk], bx, by);
            }
        }

        // online softmax over the 4-lane row group (scale already folded into Q)
        float mx0 = -1e30f;
        float mx1 = -1e30f;
#pragma unroll
        for (int nt = 0; nt < 8; nt++) {
            mx0 = fmaxf(mx0, fmaxf(s[nt][0], s[nt][1]));
            mx1 = fmaxf(mx1, fmaxf(s[nt][2], s[nt][3]));
        }
        mx0 = fmaxf(mx0, __shfl_xor_sync(0xFFFFFFFFu, mx0, 1));
        mx0 = fmaxf(mx0, __shfl_xor_sync(0xFFFFFFFFu, mx0, 2));
        mx1 = fmaxf(mx1, __shfl_xor_sync(0xFFFFFFFFu, mx1, 1));
        mx1 = fmaxf(mx1, __shfl_xor_sync(0xFFFFFFFFu, mx1, 2));

        float mn0 = fmaxf(m0, mx0);
        float mn1 = fmaxf(m1, mx1);
        float al0 = __expf(m0 - mn0);
        float al1 = __expf(m1 - mn1);
        m0 = mn0;
        m1 = mn1;

        float rs0 = 0.f;
        float rs1 = 0.f;
#pragma unroll
        for (int nt = 0; nt < 8; nt++) {
            s[nt][0] = __expf(s[nt][0] - mn0);
            s[nt][1] = __expf(s[nt][1] - mn0);
            s[nt][2] = __expf(s[nt][2] - mn1);
            s[nt][3] = __expf(s[nt][3] - mn1);
            rs0 += s[nt][0] + s[nt][1];
            rs1 += s[nt][2] + s[nt][3];
        }
        rs0 += __shfl_xor_sync(0xFFFFFFFFu, rs0, 1);
        rs0 += __shfl_xor_sync(0xFFFFFFFFu, rs0, 2);
        rs1 += __shfl_xor_sync(0xFFFFFFFFu, rs1, 1);
        rs1 += __shfl_xor_sync(0xFFFFFFFFu, rs1, 2);
        l0 = l0 * al0 + rs0;
        l1 = l1 * al1 + rs1;

#pragma unroll
        for (int nt = 0; nt < 8; nt++) {
            o[nt][0] *= al0;
            o[nt][1] *= al0;
            o[nt][2] *= al1;
            o[nt][3] *= al1;
        }

        // O += P V (P A-frags directly from S registers)
#pragma unroll
        for (int kk = 0; kk < 4; kk++) {
            unsigned pa[4];
            pa[0] = pack_h2(s[2 * kk][0],     s[2 * kk][1]);
            pa[1] = pack_h2(s[2 * kk][2],     s[2 * kk][3]);
            pa[2] = pack_h2(s[2 * kk + 1][0], s[2 * kk + 1][1]);
            pa[3] = pack_h2(s[2 * kk + 1][2], s[2 * kk + 1][3]);

            unsigned bfr[16];
#pragma unroll
            for (int ntp = 0; ntp < 4; ntp++)
                frag_b_kn(bfr + 4 * ntp, Vp, KSTR, kk * 16, ntp * 16, lane);
#pragma unroll
            for (int nt = 0; nt < 8; nt++) {
                unsigned bx = bfr[(nt >> 1) * 4 + (nt & 1) * 2];
                unsigned by = bfr[(nt >> 1) * 4 + (nt & 1) * 2 + 1];
                mma16816(o[nt], pa, bx, by);
            }
        }
        __syncthreads();   // all reads of this buffer done before it is reloaded
    }

    // normalize + write fp16 [B*N, H*d]
    float inv0 = 1.f / l0;
    float inv1 = 1.f / l1;
    const int er = lane >> 2;
    const int ec = (lane & 3) * 2;
    __half* Ab = g_Ah + (size_t)(bi * NSEQ + qtile * 64 + wid * 16) * DMODEL + hh * DHEAD;
    for (int nt = 0; nt < 8; nt++) {
        int col = nt * 8 + ec;
        *(__half2*)&Ab[(size_t)er * DMODEL + col] =
            __floats2half2_rn(o[nt][0] * inv0, o[nt][1] * inv0);
        *(__half2*)&Ab[(size_t)(er + 8) * DMODEL + col] =
            __floats2half2_rn(o[nt][2] * inv1, o[nt][3] * inv1);
    }
}

// ---------------------------------------------------------------------------
extern "C" void kernel_launch(void* const* d_in, const int* in_sizes, int n_in,
                              void* d_out, int out_size)
{
    (void)in_sizes; (void)n_in; (void)out_size;
    const float* x  = (const float*)d_in[0];
    const float* Wq = (const float*)d_in[1];
    const float* Wk = (const float*)d_in[2];
    const float* Wv = (const float*)d_in[3];
    const float* Wo = (const float*)d_in[4];
    const float* bo = (const float*)d_in[5];
    float* out = (float*)d_out;

    cvt_all<<<8192, 256>>>(x, Wq, Wk, Wv, Wo);

    dim3 qkvgrid(DMODEL / 128, MTOT / 128, 3);     // (8, 32, 3) fused Q/K/V
    gemm_h<<<qkvgrid, 256>>>(1, 0, (float*)0, (const float*)0);
    attn_h<<<dim3(NSEQ / 64, 2 * NHEAD), 128>>>();
    gemm_h<<<dim3(DMODEL / 128, MTOT / 128, 1), 256>>>(0, 3, out, bo);
}

// round 7
// speedup vs baseline: 6.3859x; 1.0147x over previous
#include <cuda_runtime.h>
#include <cuda_fp16.h>
#include <math.h>
#include <stdint.h>

#define MTOT   4096
#define NSEQ   2048
#define DMODEL 1024
#define NHEAD  16
#define DHEAD  64

// ---------------- scratch (allocation-free rule) ----------------
__device__ __half g_xh [MTOT * DMODEL];
__device__ __half g_Wqh[DMODEL * DMODEL];
__device__ __half g_Wkh[DMODEL * DMODEL];
__device__ __half g_Wvh[DMODEL * DMODEL];
__device__ __half g_Woh[DMODEL * DMODEL];
__device__ __half g_Qh [MTOT * DMODEL];   // pre-scaled by 1/8
__device__ __half g_Kh [MTOT * DMODEL];
__device__ __half g_Vh [MTOT * DMODEL];
__device__ __half g_Ah [MTOT * DMODEL];

// ---------------- helpers ----------------
__device__ __forceinline__ unsigned sptr(const void* p)
{
    return (unsigned)__cvta_generic_to_shared(p);
}

__device__ __forceinline__ void ldm_x4(unsigned* r, unsigned a)
{
    asm volatile("ldmatrix.sync.aligned.m8n8.x4.shared.b16 {%0,%1,%2,%3}, [%4];"
                 : "=r"(r[0]), "=r"(r[1]), "=r"(r[2]), "=r"(r[3]) : "r"(a));
}

__device__ __forceinline__ void ldm_x4_t(unsigned* r, unsigned a)
{
    asm volatile("ldmatrix.sync.aligned.m8n8.x4.trans.shared.b16 {%0,%1,%2,%3}, [%4];"
                 : "=r"(r[0]), "=r"(r[1]), "=r"(r[2]), "=r"(r[3]) : "r"(a));
}

__device__ __forceinline__ void mma16816(float* d, const unsigned* a,
                                         unsigned b0, unsigned b1)
{
    asm volatile(
        "mma.sync.aligned.m16n8k16.row.col.f32.f16.f16.f32 "
        "{%0,%1,%2,%3},{%4,%5,%6,%7},{%8,%9},{%0,%1,%2,%3};"
        : "+f"(d[0]), "+f"(d[1]), "+f"(d[2]), "+f"(d[3])
        : "r"(a[0]), "r"(a[1]), "r"(a[2]), "r"(a[3]), "r"(b0), "r"(b1));
}

__device__ __forceinline__ unsigned pack_h2(float x, float y)
{
    __half2 t = __floats2half2_rn(x, y);
    return *(unsigned*)&t;
}

__device__ __forceinline__ void cpa16(unsigned dst, const void* src)
{
    asm volatile("cp.async.cg.shared.global [%0], [%1], 16;"
                 :: "r"(dst), "l"(__cvta_generic_to_global(src)) : "memory");
}

__device__ __forceinline__ void cpa_commit()
{
    asm volatile("cp.async.commit_group;" ::: "memory");
}

__device__ __forceinline__ void cpa_wait0()
{
    asm volatile("cp.async.wait_group 0;" ::: "memory");
}

__device__ __forceinline__ void cpa_wait1()
{
    asm volatile("cp.async.wait_group 1;" ::: "memory");
}

__device__ __forceinline__ void cpa_wait2()
{
    asm volatile("cp.async.wait_group 2;" ::: "memory");
}

__device__ __forceinline__ void frag_a(unsigned* fr, const __half* base,
                                       int str, int row0, int col0, int lane)
{
    int gg = lane >> 3;
    int lr = lane & 7;
    int row = row0 + (gg & 1) * 8 + lr;
    int col = col0 + (gg >> 1) * 8;
    ldm_x4(fr, sptr(base + row * str + col));
}

__device__ __forceinline__ void frag_b_nk(unsigned* fr4, const __half* base,
                                          int str, int n0, int k0, int lane)
{
    int gg = lane >> 3;
    int lr = lane & 7;
    int row = n0 + (gg >> 1) * 8 + lr;
    int col = k0 + (gg & 1) * 8;
    ldm_x4(fr4, sptr(base + row * str + col));
}

__device__ __forceinline__ void frag_b_kn(unsigned* fr4, const __half* base,
                                          int str, int k0, int n0, int lane)
{
    int gg = lane >> 3;
    int lr = lane & 7;
    int row = k0 + (gg & 1) * 8 + lr;
    int col = n0 + (gg >> 1) * 8;
    ldm_x4_t(fr4, sptr(base + row * str + col));
}

// ---------------- single fused fp32 -> fp16 conversion ----------------
__global__ void cvt_all(const float* __restrict__ x,
                        const float* __restrict__ Wq,
                        const float* __restrict__ Wk,
                        const float* __restrict__ Wv,
                        const float* __restrict__ Wo)
{
    int i = blockIdx.x * blockDim.x + threadIdx.x;
    const float* src;
    __half2* dst;
    int j;
    if (i < 1048576) {
        src = x;  dst = (__half2*)g_xh;  j = i;
    } else {
        int t = i - 1048576;
        int w = t >> 18;
        j = t & 262143;
        if (w == 0)      { src = Wq; dst = (__half2*)g_Wqh; }
        else if (w == 1) { src = Wk; dst = (__half2*)g_Wkh; }
        else if (w == 2) { src = Wv; dst = (__half2*)g_Wvh; }
        else             { src = Wo; dst = (__half2*)g_Woh; }
    }
    float4 v = ((const float4*)src)[j];
    dst[2 * j]     = __floats2half2_rn(v.x, v.y);
    dst[2 * j + 1] = __floats2half2_rn(v.z, v.w);
}

// ---------------- fp16 tensor-core GEMM: 128x128x32, 4-stage cp.async ----------------
#define ASTR 40
#define BSTR 136
#define G_A_BYTES (128 * ASTR * 2)              // 10240
#define G_B_BYTES (32 * BSTR * 2)               // 8704
#define G_STAGE   (G_A_BYTES + G_B_BYTES)       // 18944
#define GSTAGES   4
#define G_SMEM    (GSTAGES * G_STAGE)           // 75776

__global__ __launch_bounds__(256, 2)
void gemm_h(int qkv, int dsel_in,
            float* __restrict__ Cf, const float* __restrict__ bias)
{
    extern __shared__ __align__(16) char gsm[];

    const int sel = qkv ? (int)blockIdx.z : dsel_in;

    const __half* __restrict__ A = (sel == 3) ? g_Ah : g_xh;
    const __half* __restrict__ B;
    if (sel == 0)      B = g_Wqh;
    else if (sel == 1) B = g_Wkh;
    else if (sel == 2) B = g_Wvh;
    else               B = g_Woh;
    __half* __restrict__ Ch;
    if (sel == 0)      Ch = g_Qh;
    else if (sel == 1) Ch = g_Kh;
    else if (sel == 2) Ch = g_Vh;
    else               Ch = (__half*)0;

    const int tid  = threadIdx.x;
    const int lane = tid & 31;
    const int wid  = tid >> 5;
    const int wm   = (wid >> 1) * 32;
    const int wn   = (wid & 1) * 64;
    const int bm   = blockIdx.y * 128;
    const int bn   = blockIdx.x * 128;

    // loader mapping: 512 16B chunks per tile, 2 per thread
    const int ca_row0 = tid >> 1;                // A: chunks c = tid*2, tid*2+1
    const int cb_row  = tid >> 3;                // B: rows 0..31 (x8 threads)
    const int cb_nc   = (tid & 7) * 2;           // B: 2 consecutive n-chunks

    auto a_tile = [&](int st) -> __half* {
        return (__half*)(gsm + st * G_STAGE);
    };
    auto b_tile = [&](int st) -> __half* {
        return (__half*)(gsm + st * G_STAGE + G_A_BYTES);
    };

    auto load_stage = [&](int s) {
        const int st = s & (GSTAGES - 1);
        __half* As = a_tile(st);
        __half* Bs = b_tile(st);
        const __half* Ap = A + (size_t)(bm + ca_row0) * DMODEL + s * 32;
        // A: each thread loads row ca_row0, k-chunks 0 and 2 (16 halfs total? no:
        // row has 32 halfs = 4 chunks; 256 threads cover 128 rows x 2 chunks each)
        {
            int kc = (tid & 1) * 2;              // unused path guard
            (void)kc;
        }
        // A: thread t handles row t>>1, chunk pair ((t&1)*2, (t&1)*2+1)
        const int arow = tid >> 1;
        const int akc  = (tid & 1) * 2;
        const __half* Apr = A + (size_t)(bm + arow) * DMODEL + s * 32 + akc * 8;
        cpa16(sptr(As + arow * ASTR + akc * 8),       Apr);
        cpa16(sptr(As + arow * ASTR + (akc + 1) * 8), Apr + 8);
        // B: thread t handles row t>>3, n-chunks cb_nc, cb_nc+1
        const __half* Bpr = B + (size_t)(s * 32 + cb_row) * DMODEL + bn + cb_nc * 8;
        cpa16(sptr(Bs + cb_row * BSTR + cb_nc * 8),       Bpr);
        cpa16(sptr(Bs + cb_row * BSTR + (cb_nc + 1) * 8), Bpr + 8);
        cpa_commit();
        (void)Ap;
        (void)ca_row0;
    };

    float acc[2][8][4];
    for (int mt = 0; mt < 2; mt++)
        for (int nt = 0; nt < 8; nt++)
            for (int c = 0; c < 4; c++)
                acc[mt][nt][c] = 0.f;

    const int NKT = DMODEL / 32;   // 32

    load_stage(0);
    load_stage(1);
    load_stage(2);

    for (int kt = 0; kt < NKT; kt++) {
        if (kt <= NKT - 3)      cpa_wait2();
        else if (kt == NKT - 2) cpa_wait1();
        else                    cpa_wait0();
        __syncthreads();

        if (kt + 3 < NKT)
            load_stage(kt + 3);   // overwrites buffer (kt-1)&3: compute done, sync passed

        const int st = kt & (GSTAGES - 1);
        const __half* As = a_tile(st);
        const __half* Bs = b_tile(st);

#pragma unroll
        for (int ks = 0; ks < 2; ks++) {
            int k0 = ks * 16;
            unsigned af0[4];
            unsigned af1[4];
            frag_a(af0, As, ASTR, wm,      k0, lane);
            frag_a(af1, As, ASTR, wm + 16, k0, lane);
            unsigned bf[16];
#pragma unroll
            for (int ntp = 0; ntp < 4; ntp++)
                frag_b_kn(bf + 4 * ntp, Bs, BSTR, k0, wn + ntp * 16, lane);
#pragma unroll
            for (int nt = 0; nt < 8; nt++) {
                unsigned bx = bf[(nt >> 1) * 4 + (nt & 1) * 2];
                unsigned by = bf[(nt >> 1) * 4 + (nt & 1) * 2 + 1];
                mma16816(acc[0][nt], af0, bx, by);
                mma16816(acc[1][nt], af1, bx, by);
            }
        }
        __syncthreads();   // all reads of stage kt done before it is reloaded
    }

    const int er = lane >> 2;
    const int ec = (lane & 3) * 2;
    if (sel < 3) {
        const float sc = (sel == 0) ? 0.125f : 1.0f;   // fold attention scale into Q
        for (int mt = 0; mt < 2; mt++) {
            for (int nt = 0; nt < 8; nt++) {
                size_t row = (size_t)(bm + wm + mt * 16 + er);
                int    col = bn + wn + nt * 8 + ec;
                *(__half2*)&Ch[row * DMODEL + col] =
                    __floats2half2_rn(acc[mt][nt][0] * sc, acc[mt][nt][1] * sc);
                *(__half2*)&Ch[(row + 8) * DMODEL + col] =
                    __floats2half2_rn(acc[mt][nt][2] * sc, acc[mt][nt][3] * sc);
            }
        }
    } else {
        for (int mt = 0; mt < 2; mt++) {
            for (int nt = 0; nt < 8; nt++) {
                size_t row = (size_t)(bm + wm + mt * 16 + er);
                int    col = bn + wn + nt * 8 + ec;
                float bv0 = bias[col];
                float bv1 = bias[col + 1];
                *(float2*)&Cf[row * DMODEL + col] =
                    make_float2(acc[mt][nt][0] + bv0, acc[mt][nt][1] + bv1);
                *(float2*)&Cf[(row + 8) * DMODEL + col] =
                    make_float2(acc[mt][nt][2] + bv0, acc[mt][nt][3] + bv1);
            }
        }
    }
}

// ---------------- flash attention, fp16 mma.sync, cp.async double buffer ----------------
#define KSTR 72
#define NTILES (NSEQ / 64)

__global__ __launch_bounds__(128, 4)
void attn_h()
{
    __shared__ __align__(16) __half Ks[2][64 * KSTR];
    __shared__ __align__(16) __half Vs[2][64 * KSTR];

    const int tid   = threadIdx.x;
    const int lane  = tid & 31;
    const int wid   = tid >> 5;
    const int qtile = blockIdx.x;
    const int bi    = blockIdx.y >> 4;
    const int hh    = blockIdx.y & 15;

    const __half* Qb = g_Qh + (size_t)(bi * NSEQ + qtile * 64) * DMODEL + hh * DHEAD;
    const __half* Kb = g_Kh + (size_t)(bi * NSEQ) * DMODEL + hh * DHEAD;
    const __half* Vb = g_Vh + (size_t)(bi * NSEQ) * DMODEL + hh * DHEAD;

    const int srow = tid >> 3;
    const int scol = (tid & 7) * 8;

#pragma unroll
    for (int u = 0; u < 4; u++) {
        int row = srow + u * 16;
        *(uint4*)&Ks[0][row * KSTR + scol] =
            *(const uint4*)(Qb + (size_t)row * DMODEL + scol);
    }
    __syncthreads();

    unsigned qa[4][4];
#pragma unroll
    for (int kk = 0; kk < 4; kk++)
        frag_a(qa[kk], Ks[0], KSTR, wid * 16, kk * 16, lane);
    __syncthreads();

    auto load_kv = [&](int it, int bf) {
        const __half* Kt = Kb + (size_t)it * 64 * DMODEL;
        const __half* Vt = Vb + (size_t)it * 64 * DMODEL;
#pragma unroll
        for (int u = 0; u < 4; u++) {
            int row = srow + u * 16;
            unsigned off = (unsigned)(row * KSTR + scol);
            cpa16(sptr(&Ks[bf][off]), Kt + (size_t)row * DMODEL + scol);
            cpa16(sptr(&Vs[bf][off]), Vt + (size_t)row * DMODEL + scol);
        }
        cpa_commit();
    };

    float m0 = -1e30f;
    float m1 = -1e30f;
    float l0 = 0.f;
    float l1 = 0.f;
    float o[8][4];
    for (int nt = 0; nt < 8; nt++)
        for (int c = 0; c < 4; c++)
            o[nt][c] = 0.f;

    load_kv(0, 0);

    for (int it = 0; it < NTILES; it++) {
        const int buf = it & 1;
        if (it + 1 < NTILES) {
            load_kv(it + 1, buf ^ 1);
            cpa_wait1();
        } else {
            cpa_wait0();
        }
        __syncthreads();

        const __half* Kp = Ks[buf];
        const __half* Vp = Vs[buf];

        float s[8][4];
        for (int nt = 0; nt < 8; nt++)
            for (int c = 0; c < 4; c++)
                s[nt][c] = 0.f;

#pragma unroll
        for (int kk = 0; kk < 4; kk++) {
            unsigned bfr[16];
#pragma unroll
            for (int ntp = 0; ntp < 4; ntp++)
                frag_b_nk(bfr + 4 * ntp, Kp, KSTR, ntp * 16, kk * 16, lane);
#pragma unroll
            for (int nt = 0; nt < 8; nt++) {
                unsigned bx = bfr[(nt >> 1) * 4 + (nt & 1) * 2];
                unsigned by = bfr[(nt >> 1) * 4 + (nt & 1) * 2 + 1];
                mma16816(s[nt], qa[kk], bx, by);
            }
        }

        float mx0 = -1e30f;
        float mx1 = -1e30f;
#pragma unroll
        for (int nt = 0; nt < 8; nt++) {
            mx0 = fmaxf(mx0, fmaxf(s[nt][0], s[nt][1]));
            mx1 = fmaxf(mx1, fmaxf(s[nt][2], s[nt][3]));
        }
        mx0 = fmaxf(mx0, __shfl_xor_sync(0xFFFFFFFFu, mx0, 1));
        mx0 = fmaxf(mx0, __shfl_xor_sync(0xFFFFFFFFu, mx0, 2));
        mx1 = fmaxf(mx1, __shfl_xor_sync(0xFFFFFFFFu, mx1, 1));
        mx1 = fmaxf(mx1, __shfl_xor_sync(0xFFFFFFFFu, mx1, 2));

        float mn0 = fmaxf(m0, mx0);
        float mn1 = fmaxf(m1, mx1);
        float al0 = __expf(m0 - mn0);
        float al1 = __expf(m1 - mn1);
        m0 = mn0;
        m1 = mn1;

        float rs0 = 0.f;
        float rs1 = 0.f;
#pragma unroll
        for (int nt = 0; nt < 8; nt++) {
            s[nt][0] = __expf(s[nt][0] - mn0);
            s[nt][1] = __expf(s[nt][1] - mn0);
            s[nt][2] = __expf(s[nt][2] - mn1);
            s[nt][3] = __expf(s[nt][3] - mn1);
            rs0 += s[nt][0] + s[nt][1];
            rs1 += s[nt][2] + s[nt][3];
        }
        rs0 += __shfl_xor_sync(0xFFFFFFFFu, rs0, 1);
        rs0 += __shfl_xor_sync(0xFFFFFFFFu, rs0, 2);
        rs1 += __shfl_xor_sync(0xFFFFFFFFu, rs1, 1);
        rs1 += __shfl_xor_sync(0xFFFFFFFFu, rs1, 2);
        l0 = l0 * al0 + rs0;
        l1 = l1 * al1 + rs1;

#pragma unroll
        for (int nt = 0; nt < 8; nt++) {
            o[nt][0] *= al0;
            o[nt][1] *= al0;
            o[nt][2] *= al1;
            o[nt][3] *= al1;
        }

#pragma unroll
        for (int kk = 0; kk < 4; kk++) {
            unsigned pa[4];
            pa[0] = pack_h2(s[2 * kk][0],     s[2 * kk][1]);
            pa[1] = pack_h2(s[2 * kk][2],     s[2 * kk][3]);
            pa[2] = pack_h2(s[2 * kk + 1][0], s[2 * kk + 1][1]);
            pa[3] = pack_h2(s[2 * kk + 1][2], s[2 * kk + 1][3]);

            unsigned bfr[16];
#pragma unroll
            for (int ntp = 0; ntp < 4; ntp++)
                frag_b_kn(bfr + 4 * ntp, Vp, KSTR, kk * 16, ntp * 16, lane);
#pragma unroll
            for (int nt = 0; nt < 8; nt++) {
                unsigned bx = bfr[(nt >> 1) * 4 + (nt & 1) * 2];
                unsigned by = bfr[(nt >> 1) * 4 + (nt & 1) * 2 + 1];
                mma16816(o[nt], pa, bx, by);
            }
        }
        __syncthreads();
    }

    float inv0 = 1.f / l0;
    float inv1 = 1.f / l1;
    const int er = lane >> 2;
    const int ec = (lane & 3) * 2;
    __half* Ab = g_Ah + (size_t)(bi * NSEQ + qtile * 64 + wid * 16) * DMODEL + hh * DHEAD;
    for (int nt = 0; nt < 8; nt++) {
        int col = nt * 8 + ec;
        *(__half2*)&Ab[(size_t)er * DMODEL + col] =
            __floats2half2_rn(o[nt][0] * inv0, o[nt][1] * inv0);
        *(__half2*)&Ab[(size_t)(er + 8) * DMODEL + col] =
            __floats2half2_rn(o[nt][2] * inv1, o[nt][3] * inv1);
    }
}

// ---------------------------------------------------------------------------
extern "C" void kernel_launch(void* const* d_in, const int* in_sizes, int n_in,
                              void* d_out, int out_size)
{
    (void)in_sizes; (void)n_in; (void)out_size;
    const float* x  = (const float*)d_in[0];
    const float* Wq = (const float*)d_in[1];
    const float* Wk = (const float*)d_in[2];
    const float* Wv = (const float*)d_in[3];
    const float* Wo = (const float*)d_in[4];
    const float* bo = (const float*)d_in[5];
    float* out = (float*)d_out;

    cudaFuncSetAttribute(gemm_h,
                         cudaFuncAttributeMaxDynamicSharedMemorySize, G_SMEM);

    cvt_all<<<8192, 256>>>(x, Wq, Wk, Wv, Wo);

    dim3 qkvgrid(DMODEL / 128, MTOT / 128, 3);
    gemm_h<<<qkvgrid, 256, G_SMEM>>>(1, 0, (float*)0, (const float*)0);
    attn_h<<<dim3(NSEQ / 64, 2 * NHEAD), 128>>>();
    gemm_h<<<dim3(DMODEL / 128, MTOT / 128, 1), 256, G_SMEM>>>(0, 3, out, bo);
}

// round 8
// speedup vs baseline: 6.3938x; 1.0012x over previous
#include <cuda_runtime.h>
#include <cuda_fp16.h>
#include <math.h>
#include <stdint.h>

#define MTOT   4096
#define NSEQ   2048
#define DMODEL 1024
#define NHEAD  16
#define DHEAD  64

// ---------------- scratch (allocation-free rule) ----------------
__device__ __half g_xh [MTOT * DMODEL];
__device__ __half g_Wqh[DMODEL * DMODEL];
__device__ __half g_Wkh[DMODEL * DMODEL];
__device__ __half g_Wvh[DMODEL * DMODEL];
__device__ __half g_Woh[DMODEL * DMODEL];
__device__ __half g_Qh [MTOT * DMODEL];   // pre-scaled by 1/8
__device__ __half g_Kh [MTOT * DMODEL];
__device__ __half g_Vh [MTOT * DMODEL];
__device__ __half g_Ah [MTOT * DMODEL];

// ---------------- helpers ----------------
__device__ __forceinline__ unsigned sptr(const void* p)
{
    return (unsigned)__cvta_generic_to_shared(p);
}

__device__ __forceinline__ void ldm_x4(unsigned* r, unsigned a)
{
    asm volatile("ldmatrix.sync.aligned.m8n8.x4.shared.b16 {%0,%1,%2,%3}, [%4];"
                 : "=r"(r[0]), "=r"(r[1]), "=r"(r[2]), "=r"(r[3]) : "r"(a));
}

__device__ __forceinline__ void ldm_x4_t(unsigned* r, unsigned a)
{
    asm volatile("ldmatrix.sync.aligned.m8n8.x4.trans.shared.b16 {%0,%1,%2,%3}, [%4];"
                 : "=r"(r[0]), "=r"(r[1]), "=r"(r[2]), "=r"(r[3]) : "r"(a));
}

__device__ __forceinline__ void mma16816(float* d, const unsigned* a,
                                         unsigned b0, unsigned b1)
{
    asm volatile(
        "mma.sync.aligned.m16n8k16.row.col.f32.f16.f16.f32 "
        "{%0,%1,%2,%3},{%4,%5,%6,%7},{%8,%9},{%0,%1,%2,%3};"
        : "+f"(d[0]), "+f"(d[1]), "+f"(d[2]), "+f"(d[3])
        : "r"(a[0]), "r"(a[1]), "r"(a[2]), "r"(a[3]), "r"(b0), "r"(b1));
}

__device__ __forceinline__ unsigned pack_h2(float x, float y)
{
    __half2 t = __floats2half2_rn(x, y);
    return *(unsigned*)&t;
}

__device__ __forceinline__ void cpa16(unsigned dst, const void* src)
{
    asm volatile("cp.async.cg.shared.global [%0], [%1], 16;"
                 :: "r"(dst), "l"(__cvta_generic_to_global(src)) : "memory");
}

__device__ __forceinline__ void cpa_commit()
{
    asm volatile("cp.async.commit_group;" ::: "memory");
}

__device__ __forceinline__ void cpa_wait0()
{
    asm volatile("cp.async.wait_group 0;" ::: "memory");
}

__device__ __forceinline__ void cpa_wait1()
{
    asm volatile("cp.async.wait_group 1;" ::: "memory");
}

__device__ __forceinline__ void cpa_wait2()
{
    asm volatile("cp.async.wait_group 2;" ::: "memory");
}

__device__ __forceinline__ void frag_a(unsigned* fr, const __half* base,
                                       int str, int row0, int col0, int lane)
{
    int gg = lane >> 3;
    int lr = lane & 7;
    int row = row0 + (gg & 1) * 8 + lr;
    int col = col0 + (gg >> 1) * 8;
    ldm_x4(fr, sptr(base + row * str + col));
}

__device__ __forceinline__ void frag_b_nk(unsigned* fr4, const __half* base,
                                          int str, int n0, int k0, int lane)
{
    int gg = lane >> 3;
    int lr = lane & 7;
    int row = n0 + (gg >> 1) * 8 + lr;
    int col = k0 + (gg & 1) * 8;
    ldm_x4(fr4, sptr(base + row * str + col));
}

__device__ __forceinline__ void frag_b_kn(unsigned* fr4, const __half* base,
                                          int str, int k0, int n0, int lane)
{
    int gg = lane >> 3;
    int lr = lane & 7;
    int row = k0 + (gg & 1) * 8 + lr;
    int col = n0 + (gg >> 1) * 8;
    ldm_x4_t(fr4, sptr(base + row * str + col));
}

// ---------------- single fused fp32 -> fp16 conversion ----------------
__global__ void cvt_all(const float* __restrict__ x,
                        const float* __restrict__ Wq,
                        const float* __restrict__ Wk,
                        const float* __restrict__ Wv,
                        const float* __restrict__ Wo)
{
    int i = blockIdx.x * blockDim.x + threadIdx.x;
    const float* src;
    __half2* dst;
    int j;
    if (i < 1048576) {
        src = x;  dst = (__half2*)g_xh;  j = i;
    } else {
        int t = i - 1048576;
        int w = t >> 18;
        j = t & 262143;
        if (w == 0)      { src = Wq; dst = (__half2*)g_Wqh; }
        else if (w == 1) { src = Wk; dst = (__half2*)g_Wkh; }
        else if (w == 2) { src = Wv; dst = (__half2*)g_Wvh; }
        else             { src = Wo; dst = (__half2*)g_Woh; }
    }
    float4 v = ((const float4*)src)[j];
    dst[2 * j]     = __floats2half2_rn(v.x, v.y);
    dst[2 * j + 1] = __floats2half2_rn(v.z, v.w);
}

// ---------------- fp16 tensor-core GEMM: 256x128 CTA, m64n64 warps ----------------
#define ASTR 40
#define BSTR 136
#define G2_A_BYTES (256 * ASTR * 2)              // 20480
#define G2_B_BYTES (32 * BSTR * 2)               // 8704
#define G2_STAGE   (G2_A_BYTES + G2_B_BYTES)     // 29184
#define G2_STAGES  4
#define G2_SMEM    (G2_STAGES * G2_STAGE)        // 116736

__global__ __launch_bounds__(256, 1)
void gemm_h(int qkv, int dsel_in,
            float* __restrict__ Cf, const float* __restrict__ bias)
{
    extern __shared__ __align__(16) char gsm[];

    const int sel = qkv ? (int)blockIdx.z : dsel_in;

    const __half* __restrict__ A = (sel == 3) ? g_Ah : g_xh;
    const __half* __restrict__ B;
    if (sel == 0)      B = g_Wqh;
    else if (sel == 1) B = g_Wkh;
    else if (sel == 2) B = g_Wvh;
    else               B = g_Woh;
    __half* __restrict__ Ch;
    if (sel == 0)      Ch = g_Qh;
    else if (sel == 1) Ch = g_Kh;
    else if (sel == 2) Ch = g_Vh;
    else               Ch = (__half*)0;

    const int tid  = threadIdx.x;
    const int lane = tid & 31;
    const int wid  = tid >> 5;
    const int wm   = (wid & 3) * 64;     // 4 warps along M (256)
    const int wn   = (wid >> 2) * 64;    // 2 warps along N (128)
    const int bm   = blockIdx.y * 256;
    const int bn   = blockIdx.x * 128;

    auto load_stage = [&](int s) {
        const int st = s & (G2_STAGES - 1);
        __half* As = (__half*)(gsm + st * G2_STAGE);
        __half* Bs = (__half*)(gsm + st * G2_STAGE + G2_A_BYTES);
        // A: 256 rows x 32 halfs = 1024 x 16B chunks; chunk-major for coalescing
#pragma unroll
        for (int i = 0; i < 4; i++) {
            int c   = i * 256 + tid;
            int row = c >> 2;
            int kc  = c & 3;
            cpa16(sptr(As + row * ASTR + kc * 8),
                  A + (size_t)(bm + row) * DMODEL + s * 32 + kc * 8);
        }
        // B: 32 rows x 128 halfs = 512 x 16B chunks
#pragma unroll
        for (int i = 0; i < 2; i++) {
            int c   = i * 256 + tid;
            int row = c >> 4;
            int nc  = c & 15;
            cpa16(sptr(Bs + row * BSTR + nc * 8),
                  B + (size_t)(s * 32 + row) * DMODEL + bn + nc * 8);
        }
        cpa_commit();
    };

    float acc[4][8][4];
    for (int mt = 0; mt < 4; mt++)
        for (int nt = 0; nt < 8; nt++)
            for (int c = 0; c < 4; c++)
                acc[mt][nt][c] = 0.f;

    const int NKT = DMODEL / 32;   // 32

    load_stage(0);
    load_stage(1);
    load_stage(2);

    for (int kt = 0; kt < NKT; kt++) {
        if (kt <= NKT - 3)      cpa_wait2();
        else if (kt == NKT - 2) cpa_wait1();
        else                    cpa_wait0();
        __syncthreads();
        // After this barrier every thread has finished compute of kt-1, so
        // buffer (kt-1)&3 == (kt+3)&3 is free to overwrite.
        if (kt + 3 < NKT)
            load_stage(kt + 3);

        const int st = kt & (G2_STAGES - 1);
        const __half* As = (const __half*)(gsm + st * G2_STAGE);
        const __half* Bs = (const __half*)(gsm + st * G2_STAGE + G2_A_BYTES);

#pragma unroll
        for (int ks = 0; ks < 2; ks++) {
            int k0 = ks * 16;
            unsigned af[4][4];
#pragma unroll
            for (int mt = 0; mt < 4; mt++)
                frag_a(af[mt], As, ASTR, wm + mt * 16, k0, lane);
            unsigned bf[16];
#pragma unroll
            for (int ntp = 0; ntp < 4; ntp++)
                frag_b_kn(bf + 4 * ntp, Bs, BSTR, k0, wn + ntp * 16, lane);
#pragma unroll
            for (int nt = 0; nt < 8; nt++) {
                unsigned bx = bf[(nt >> 1) * 4 + (nt & 1) * 2];
                unsigned by = bf[(nt >> 1) * 4 + (nt & 1) * 2 + 1];
#pragma unroll
                for (int mt = 0; mt < 4; mt++)
                    mma16816(acc[mt][nt], af[mt], bx, by);
            }
        }
        // no trailing barrier: next iteration's barrier provides the hazard edge
    }

    const int er = lane >> 2;
    const int ec = (lane & 3) * 2;
    if (sel < 3) {
        const float sc = (sel == 0) ? 0.125f : 1.0f;   // fold attention scale into Q
        for (int mt = 0; mt < 4; mt++) {
            for (int nt = 0; nt < 8; nt++) {
                size_t row = (size_t)(bm + wm + mt * 16 + er);
                int    col = bn + wn + nt * 8 + ec;
                *(__half2*)&Ch[row * DMODEL + col] =
                    __floats2half2_rn(acc[mt][nt][0] * sc, acc[mt][nt][1] * sc);
                *(__half2*)&Ch[(row + 8) * DMODEL + col] =
                    __floats2half2_rn(acc[mt][nt][2] * sc, acc[mt][nt][3] * sc);
            }
        }
    } else {
        for (int mt = 0; mt < 4; mt++) {
            for (int nt = 0; nt < 8; nt++) {
                size_t row = (size_t)(bm + wm + mt * 16 + er);
                int    col = bn + wn + nt * 8 + ec;
                float bv0 = bias[col];
                float bv1 = bias[col + 1];
                *(float2*)&Cf[row * DMODEL + col] =
                    make_float2(acc[mt][nt][0] + bv0, acc[mt][nt][1] + bv1);
                *(float2*)&Cf[(row + 8) * DMODEL + col] =
                    make_float2(acc[mt][nt][2] + bv0, acc[mt][nt][3] + bv1);
            }
        }
    }
}

// ---------------- flash attention, fp16 mma.sync, cp.async double buffer ----------------
#define KSTR 72
#define NTILES (NSEQ / 64)

__global__ __launch_bounds__(128, 4)
void attn_h()
{
    __shared__ __align__(16) __half Ks[2][64 * KSTR];
    __shared__ __align__(16) __half Vs[2][64 * KSTR];

    const int tid   = threadIdx.x;
    const int lane  = tid & 31;
    const int wid   = tid >> 5;
    const int qtile = blockIdx.x;
    const int bi    = blockIdx.y >> 4;
    const int hh    = blockIdx.y & 15;

    const __half* Qb = g_Qh + (size_t)(bi * NSEQ + qtile * 64) * DMODEL + hh * DHEAD;
    const __half* Kb = g_Kh + (size_t)(bi * NSEQ) * DMODEL + hh * DHEAD;
    const __half* Vb = g_Vh + (size_t)(bi * NSEQ) * DMODEL + hh * DHEAD;

    const int srow = tid >> 3;
    const int scol = (tid & 7) * 8;

#pragma unroll
    for (int u = 0; u < 4; u++) {
        int row = srow + u * 16;
        *(uint4*)&Ks[0][row * KSTR + scol] =
            *(const uint4*)(Qb + (size_t)row * DMODEL + scol);
    }
    __syncthreads();

    unsigned qa[4][4];
#pragma unroll
    for (int kk = 0; kk < 4; kk++)
        frag_a(qa[kk], Ks[0], KSTR, wid * 16, kk * 16, lane);
    __syncthreads();

    auto load_kv = [&](int it, int bf) {
        const __half* Kt = Kb + (size_t)it * 64 * DMODEL;
        const __half* Vt = Vb + (size_t)it * 64 * DMODEL;
#pragma unroll
        for (int u = 0; u < 4; u++) {
            int row = srow + u * 16;
            unsigned off = (unsigned)(row * KSTR + scol);
            cpa16(sptr(&Ks[bf][off]), Kt + (size_t)row * DMODEL + scol);
            cpa16(sptr(&Vs[bf][off]), Vt + (size_t)row * DMODEL + scol);
        }
        cpa_commit();
    };

    float m0 = -1e30f;
    float m1 = -1e30f;
    float l0 = 0.f;
    float l1 = 0.f;
    float o[8][4];
    for (int nt = 0; nt < 8; nt++)
        for (int c = 0; c < 4; c++)
            o[nt][c] = 0.f;

    load_kv(0, 0);

    for (int it = 0; it < NTILES; it++) {
        const int buf = it & 1;
        if (it + 1 < NTILES) {
            load_kv(it + 1, buf ^ 1);
            cpa_wait1();
        } else {
            cpa_wait0();
        }
        __syncthreads();

        const __half* Kp = Ks[buf];
        const __half* Vp = Vs[buf];

        float s[8][4];
        for (int nt = 0; nt < 8; nt++)
            for (int c = 0; c < 4; c++)
                s[nt][c] = 0.f;

#pragma unroll
        for (int kk = 0; kk < 4; kk++) {
            unsigned bfr[16];
#pragma unroll
            for (int ntp = 0; ntp < 4; ntp++)
                frag_b_nk(bfr + 4 * ntp, Kp, KSTR, ntp * 16, kk * 16, lane);
#pragma unroll
            for (int nt = 0; nt < 8; nt++) {
                unsigned bx = bfr[(nt >> 1) * 4 + (nt & 1) * 2];
                unsigned by = bfr[(nt >> 1) * 4 + (nt & 1) * 2 + 1];
                mma16816(s[nt], qa[kk], bx, by);
            }
        }

        float mx0 = -1e30f;
        float mx1 = -1e30f;
#pragma unroll
        for (int nt = 0; nt < 8; nt++) {
            mx0 = fmaxf(mx0, fmaxf(s[nt][0], s[nt][1]));
            mx1 = fmaxf(mx1, fmaxf(s[nt][2], s[nt][3]));
        }
        mx0 = fmaxf(mx0, __shfl_xor_sync(0xFFFFFFFFu, mx0, 1));
        mx0 = fmaxf(mx0, __shfl_xor_sync(0xFFFFFFFFu, mx0, 2));
        mx1 = fmaxf(mx1, __shfl_xor_sync(0xFFFFFFFFu, mx1, 1));
        mx1 = fmaxf(mx1, __shfl_xor_sync(0xFFFFFFFFu, mx1, 2));

        float mn0 = fmaxf(m0, mx0);
        float mn1 = fmaxf(m1, mx1);
        float al0 = __expf(m0 - mn0);
        float al1 = __expf(m1 - mn1);
        m0 = mn0;
        m1 = mn1;

        float rs0 = 0.f;
        float rs1 = 0.f;
#pragma unroll
        for (int nt = 0; nt < 8; nt++) {
            s[nt][0] = __expf(s[nt][0] - mn0);
            s[nt][1] = __expf(s[nt][1] - mn0);
            s[nt][2] = __expf(s[nt][2] - mn1);
            s[nt][3] = __expf(s[nt][3] - mn1);
            rs0 += s[nt][0] + s[nt][1];
            rs1 += s[nt][2] + s[nt][3];
        }
        rs0 += __shfl_xor_sync(0xFFFFFFFFu, rs0, 1);
        rs0 += __shfl_xor_sync(0xFFFFFFFFu, rs0, 2);
        rs1 += __shfl_xor_sync(0xFFFFFFFFu, rs1, 1);
        rs1 += __shfl_xor_sync(0xFFFFFFFFu, rs1, 2);
        l0 = l0 * al0 + rs0;
        l1 = l1 * al1 + rs1;

#pragma unroll
        for (int nt = 0; nt < 8; nt++) {
            o[nt][0] *= al0;
            o[nt][1] *= al0;
            o[nt][2] *= al1;
            o[nt][3] *= al1;
        }

#pragma unroll
        for (int kk = 0; kk < 4; kk++) {
            unsigned pa[4];
            pa[0] = pack_h2(s[2 * kk][0],     s[2 * kk][1]);
            pa[1] = pack_h2(s[2 * kk][2],     s[2 * kk][3]);
            pa[2] = pack_h2(s[2 * kk + 1][0], s[2 * kk + 1][1]);
            pa[3] = pack_h2(s[2 * kk + 1][2], s[2 * kk + 1][3]);

            unsigned bfr[16];
#pragma unroll
            for (int ntp = 0; ntp < 4; ntp++)
                frag_b_kn(bfr + 4 * ntp, Vp, KSTR, kk * 16, ntp * 16, lane);
#pragma unroll
            for (int nt = 0; nt < 8; nt++) {
                unsigned bx = bfr[(nt >> 1) * 4 + (nt & 1) * 2];
                unsigned by = bfr[(nt >> 1) * 4 + (nt & 1) * 2 + 1];
                mma16816(o[nt], pa, bx, by);
            }
        }
        __syncthreads();
    }

    float inv0 = 1.f / l0;
    float inv1 = 1.f / l1;
    const int er = lane >> 2;
    const int ec = (lane & 3) * 2;
    __half* Ab = g_Ah + (size_t)(bi * NSEQ + qtile * 64 + wid * 16) * DMODEL + hh * DHEAD;
    for (int nt = 0; nt < 8; nt++) {
        int col = nt * 8 + ec;
        *(__half2*)&Ab[(size_t)er * DMODEL + col] =
            __floats2half2_rn(o[nt][0] * inv0, o[nt][1] * inv0);
        *(__half2*)&Ab[(size_t)(er + 8) * DMODEL + col] =
            __floats2half2_rn(o[nt][2] * inv1, o[nt][3] * inv1);
    }
}

// ---------------------------------------------------------------------------
extern "C" void kernel_launch(void* const* d_in, const int* in_sizes, int n_in,
                              void* d_out, int out_size)
{
    (void)in_sizes; (void)n_in; (void)out_size;
    const float* x  = (const float*)d_in[0];
    const float* Wq = (const float*)d_in[1];
    const float* Wk = (const float*)d_in[2];
    const float* Wv = (const float*)d_in[3];
    const float* Wo = (const float*)d_in[4];
    const float* bo = (const float*)d_in[5];
    float* out = (float*)d_out;

    cudaFuncSetAttribute(gemm_h,
                         cudaFuncAttributeMaxDynamicSharedMemorySize, G2_SMEM);

    cvt_all<<<8192, 256>>>(x, Wq, Wk, Wv, Wo);

    dim3 qkvgrid(DMODEL / 128, MTOT / 256, 3);     // (8, 16, 3)
    gemm_h<<<qkvgrid, 256, G2_SMEM>>>(1, 0, (float*)0, (const float*)0);
    attn_h<<<dim3(NSEQ / 64, 2 * NHEAD), 128>>>();
    gemm_h<<<dim3(DMODEL / 128, MTOT / 256, 1), 256, G2_SMEM>>>(0, 3, out, bo);
}